// round 2
// baseline (speedup 1.0000x reference)
#include <cuda_runtime.h>
#include <math.h>

#define TILE_E   128
#define NTHREADS 256
#define HDIM     128
#define H2DIM    64

// GEMM1: [TILE_E, 512] @ [512, 128]  (edge_repr built on the fly)
// GEMM2: [TILE_E, 128] @ [128, 64]
// GEMM3: [TILE_E, 64]  @ [64, 1]    (shfl reduction)

struct SmemLayout {
    int src_idx[TILE_E];
    int dst_idx[TILE_E];
    int idx_is_i64;                 // edge_index dtype flag (detected per block)
    int pad_[3];
    union {
        struct {
            float As[TILE_E][36];   // edge_repr k-panel (32 cols, padded to 36)
            float Bs[32][HDIM];     // W1 k-panel
        } g1;
        float W2s[HDIM][H2DIM];     // reused after GEMM1
    } u;
    float Ch[TILE_E][HDIM + 4];     // relu(h1) staging, padded
};

__global__ __launch_bounds__(NTHREADS, 2)
void link_pred_kernel(const float* __restrict__ z,
                      const void* __restrict__ ei_raw,
                      const float* __restrict__ W1,
                      const float* __restrict__ b1,
                      const float* __restrict__ W2,
                      const float* __restrict__ b2,
                      const float* __restrict__ W3,
                      const float* __restrict__ b3,
                      float* __restrict__ out,
                      int E, int nNodes)
{
    extern __shared__ char raw[];
    SmemLayout& s = *reinterpret_cast<SmemLayout*>(raw);

    const int tid = threadIdx.x;
    const int e0  = blockIdx.x * TILE_E;

    // ---- detect edge_index dtype (int64 vs harness-downcast int32) ----
    if (tid == 0) {
        const long long* e64 = (const long long*)ei_raw;
        int is64 = 1;
        #pragma unroll
        for (int i = 0; i < 8; ++i) {
            long long v = e64[i];
            if (v < 0 || v >= (long long)nNodes) { is64 = 0; break; }
        }
        s.idx_is_i64 = is64;
    }
    __syncthreads();

    // ---- stage edge indices (clamped for the ragged last tile) ----
    {
        const int is64 = s.idx_is_i64;
        int t = tid & (TILE_E - 1);
        int e = e0 + t;
        if (e >= E) e = 0;                    // deterministic safe index
        int v;
        if (tid < TILE_E) {
            v = is64 ? (int)((const long long*)ei_raw)[e]
                     : ((const int*)ei_raw)[e];
            v = min(max(v, 0), nNodes - 1);   // safety clamp
            s.src_idx[t] = v;
        } else {
            v = is64 ? (int)((const long long*)ei_raw)[(size_t)E + e]
                     : ((const int*)ei_raw)[(size_t)E + e];
            v = min(max(v, 0), nNodes - 1);
            s.dst_idx[t] = v;
        }
    }

    const int cg = tid & 15;                  // output-col group 0..15
    const int rg = tid >> 4;                  // edge-row group 0..15
    const int r0 = rg * 8;
    const int c0 = cg * 8;

    float acc[8][8];
    #pragma unroll
    for (int i = 0; i < 8; ++i)
        #pragma unroll
        for (int j = 0; j < 8; ++j) acc[i][j] = 0.f;

    // =================== GEMM1: K = 512 in 16 panels of 32 ===================
    for (int p = 0; p < 16; ++p) {
        __syncthreads();   // protects previous panel reads (+ index staging at p=0)

        const int seg   = p >> 2;             // 0:src 1:dst 2:prod 3:absdiff
        const int cbase = (p & 3) * 32;

        // ---- build A panel: edge_repr[:, p*32 .. p*32+31] ----
        #pragma unroll
        for (int it = 0; it < 4; ++it) {
            int idx = tid + it * NTHREADS;    // 0..1023
            int e   = idx >> 3;               // 0..127
            int q   = idx & 7;                // 0..7 (float4 slot)
            int col = cbase + q * 4;
            const float* zs = z + (size_t)s.src_idx[e] * HDIM + col;
            const float* zd = z + (size_t)s.dst_idx[e] * HDIM + col;
            float4 v;
            if (seg == 0) {
                v = *reinterpret_cast<const float4*>(zs);
            } else if (seg == 1) {
                v = *reinterpret_cast<const float4*>(zd);
            } else {
                float4 a4 = *reinterpret_cast<const float4*>(zs);
                float4 d4 = *reinterpret_cast<const float4*>(zd);
                if (seg == 2)
                    v = make_float4(a4.x * d4.x, a4.y * d4.y, a4.z * d4.z, a4.w * d4.w);
                else
                    v = make_float4(fabsf(a4.x - d4.x), fabsf(a4.y - d4.y),
                                    fabsf(a4.z - d4.z), fabsf(a4.w - d4.w));
            }
            *reinterpret_cast<float4*>(&s.u.g1.As[e][q * 4]) = v;
        }

        // ---- load W1 panel: rows p*32 .. p*32+31, all 128 cols ----
        #pragma unroll
        for (int it = 0; it < 4; ++it) {
            int idx = tid + it * NTHREADS;    // 0..1023
            int k   = idx >> 5;               // 0..31
            int c4  = idx & 31;               // 0..31 (float4 slot)
            float4 w = *reinterpret_cast<const float4*>(
                W1 + (size_t)(p * 32 + k) * HDIM + c4 * 4);
            *reinterpret_cast<float4*>(&s.u.g1.Bs[k][c4 * 4]) = w;
        }

        __syncthreads();

        // ---- 8x8 register-tiled inner product over the 32-deep panel ----
        #pragma unroll
        for (int k = 0; k < 32; ++k) {
            float a[8];
            #pragma unroll
            for (int i = 0; i < 8; ++i) a[i] = s.u.g1.As[r0 + i][k];
            float4 bl = *reinterpret_cast<const float4*>(&s.u.g1.Bs[k][c0]);
            float4 bh = *reinterpret_cast<const float4*>(&s.u.g1.Bs[k][c0 + 4]);
            float b[8] = {bl.x, bl.y, bl.z, bl.w, bh.x, bh.y, bh.z, bh.w};
            #pragma unroll
            for (int i = 0; i < 8; ++i)
                #pragma unroll
                for (int j = 0; j < 8; ++j)
                    acc[i][j] = fmaf(a[i], b[j], acc[i][j]);
        }
    }

    // ---- epilogue 1: +b1, relu, stage into Ch ----
    {
        float bias1[8];
        #pragma unroll
        for (int j = 0; j < 8; ++j) bias1[j] = __ldg(&b1[c0 + j]);
        #pragma unroll
        for (int i = 0; i < 8; ++i)
            #pragma unroll
            for (int j = 0; j < 8; ++j)
                s.Ch[r0 + i][c0 + j] = fmaxf(acc[i][j] + bias1[j], 0.f);
    }
    __syncthreads();

    // ---- load W2 into smem (aliases As/Bs, safe after the sync) ----
    #pragma unroll
    for (int it = 0; it < 8; ++it) {
        int idx = tid + it * NTHREADS;        // 0..2047
        int k   = idx >> 4;                   // 0..127
        int c4  = idx & 15;                   // 0..15 (float4 slot)
        float4 w = *reinterpret_cast<const float4*>(W2 + (size_t)k * H2DIM + c4 * 4);
        *reinterpret_cast<float4*>(&s.u.W2s[k][c4 * 4]) = w;
    }
    __syncthreads();

    // =================== GEMM2: [128,128] @ [128,64] ===================
    const int c2 = cg * 4;                    // 0..60
    float acc2[8][4];
    #pragma unroll
    for (int i = 0; i < 8; ++i)
        #pragma unroll
        for (int j = 0; j < 4; ++j) acc2[i][j] = 0.f;

    #pragma unroll 4
    for (int k = 0; k < HDIM; ++k) {
        float4 bv = *reinterpret_cast<const float4*>(&s.u.W2s[k][c2]);
        #pragma unroll
        for (int i = 0; i < 8; ++i) {
            float a = s.Ch[r0 + i][k];
            acc2[i][0] = fmaf(a, bv.x, acc2[i][0]);
            acc2[i][1] = fmaf(a, bv.y, acc2[i][1]);
            acc2[i][2] = fmaf(a, bv.z, acc2[i][2]);
            acc2[i][3] = fmaf(a, bv.w, acc2[i][3]);
        }
    }

    // ---- epilogue 2: +b2, relu, dot W3, 16-lane reduce, +b3, store ----
    {
        float b2v[4], w3v[4];
        #pragma unroll
        for (int j = 0; j < 4; ++j) {
            b2v[j] = __ldg(&b2[c2 + j]);
            w3v[j] = __ldg(&W3[c2 + j]);
        }
        const float bias3 = __ldg(&b3[0]);

        #pragma unroll
        for (int i = 0; i < 8; ++i) {
            float h0 = fmaxf(acc2[i][0] + b2v[0], 0.f);
            float h1 = fmaxf(acc2[i][1] + b2v[1], 0.f);
            float h2 = fmaxf(acc2[i][2] + b2v[2], 0.f);
            float h3 = fmaxf(acc2[i][3] + b2v[3], 0.f);
            float p = fmaf(h0, w3v[0], fmaf(h1, w3v[1],
                      fmaf(h2, w3v[2], h3 * w3v[3])));
            #pragma unroll
            for (int m = 8; m >= 1; m >>= 1)
                p += __shfl_xor_sync(0xffffffffu, p, m);
            if (cg == 0) {
                int e = e0 + r0 + i;
                if (e < E) out[e] = p + bias3;
            }
        }
    }
}

extern "C" void kernel_launch(void* const* d_in, const int* in_sizes, int n_in,
                              void* d_out, int out_size) {
    const float* z  = (const float*)d_in[0];
    const void*  ei = d_in[1];
    const float* W1 = (const float*)d_in[2];
    const float* b1 = (const float*)d_in[3];
    const float* W2 = (const float*)d_in[4];
    const float* b2 = (const float*)d_in[5];
    const float* W3 = (const float*)d_in[6];
    const float* b3 = (const float*)d_in[7];
    float* out = (float*)d_out;

    const int E      = out_size;              // score is [E]
    const int nNodes = in_sizes[0] / HDIM;    // z is [N, H]
    const int smem   = (int)sizeof(SmemLayout);

    cudaFuncSetAttribute(link_pred_kernel,
                         cudaFuncAttributeMaxDynamicSharedMemorySize, smem);

    const int grid = (E + TILE_E - 1) / TILE_E;
    link_pred_kernel<<<grid, NTHREADS, smem>>>(z, ei, W1, b1, W2, b2, W3, b3,
                                               out, E, nNodes);
}